// round 3
// baseline (speedup 1.0000x reference)
#include <cuda_runtime.h>
#include <math.h>

#define BB 16
#define NN 512
#define HH 128
#define EE 4
#define NE 2048          /* NN*EE */
#define NR 8192          /* BB*NN */
#define STEPS 5

// ---------------- scratch (device globals; no allocation) ----------------
__device__ float g_h[NR * HH];                 // 4 MB  current hidden state
__device__ float g_in_st[BB * NE * HH];        // 16 MB in_states  (B, N*E, H)
__device__ float g_out_st[BB * NE * HH];       // 16 MB out_states
__device__ float g_ain[NR * HH];               // 4 MB
__device__ float g_aout[NR * HH];              // 4 MB
__device__ float g_z[NR * HH];                 // 4 MB
__device__ float g_rh[NR * HH];                // 4 MB  r * h

__device__ __forceinline__ float sigmoidf_(float v) { return 1.0f / (1.0f + expf(-v)); }

// ---------------- generic 64x64x16 tiled SGEMM core ----------------
// 256 threads, 4x4 microtile per thread. A/B/epilogue supplied as lambdas.
template <class ALoad, class BLoad, class Epi>
__device__ __forceinline__ void gemm64(ALoad aload, BLoad bload, Epi epi, int K) {
  __shared__ __align__(16) float As[16][68];   // k-major, padded vs bank conflicts
  __shared__ __align__(16) float Bs[16][64];
  float acc[4][4] = {};
  const int tid = threadIdx.x;
  const int tx = tid & 15, ty = tid >> 4;
  const int ar = tid >> 2, ak = (tid & 3) << 2;   // A loader: 64 rows x 16 k
  const int bk = tid >> 4, bn = (tid & 15) << 2;  // B loader: 16 k x 64 cols

  for (int k0 = 0; k0 < K; k0 += 16) {
    float4 av = aload(ar, k0 + ak);
    As[ak + 0][ar] = av.x;
    As[ak + 1][ar] = av.y;
    As[ak + 2][ar] = av.z;
    As[ak + 3][ar] = av.w;
    float4 bv = bload(k0 + bk, bn);
    *reinterpret_cast<float4*>(&Bs[bk][bn]) = bv;
    __syncthreads();
#pragma unroll
    for (int kk = 0; kk < 16; kk++) {
      float4 a4 = *reinterpret_cast<const float4*>(&As[kk][ty << 2]);
      float4 b4 = *reinterpret_cast<const float4*>(&Bs[kk][tx << 2]);
      float a[4] = {a4.x, a4.y, a4.z, a4.w};
      float b[4] = {b4.x, b4.y, b4.z, b4.w};
#pragma unroll
      for (int i = 0; i < 4; i++)
#pragma unroll
        for (int j = 0; j < 4; j++) acc[i][j] += a[i] * b[j];
    }
    __syncthreads();
  }
  epi(acc, ty, tx);
}

// ---------------- step kernels ----------------

__global__ void copy_h_kernel(const float* __restrict__ x) {
  int i = blockIdx.x * 256 + threadIdx.x;
  g_h[i] = x[i];
}

// y = h @ W (+ bias), scattered into edge-state layout:
// y[b,n, hh*E+e]  ->  states[b, e*N + n, hh]
template <int DIR>
__global__ void proj_kernel(const float* __restrict__ W, const float* __restrict__ bias) {
  const int m0 = blockIdx.y << 6;   // row block within 8192
  const int n0 = blockIdx.x << 6;   // col block within 512
  float* dst = DIR ? g_out_st : g_in_st;
  auto aload = [&](int r, int k) {
    return *reinterpret_cast<const float4*>(&g_h[(m0 + r) * HH + k]);
  };
  auto bload = [&](int k, int n) {
    return *reinterpret_cast<const float4*>(&W[k * (HH * EE) + n0 + n]);
  };
  auto epi = [&](float (&acc)[4][4], int ty, int tx) {
#pragma unroll
    for (int i = 0; i < 4; i++) {
      int row = m0 + (ty << 2) + i;
      int b = row >> 9, n = row & (NN - 1);
#pragma unroll
      for (int j = 0; j < 4; j++) {
        int col = n0 + (tx << 2) + j;
        int e = col & 3, hh = col >> 2;
        dst[((b * EE + e) * NN + n) * HH + hh] = acc[i][j] + bias[col];
      }
    }
  };
  gemm64(aload, bload, epi, HH);
}

// a_in[b] = m_in[b] (512x2048) @ in_states[b] (2048x128); same for out.
// grid.z = 2*batch: bit0 selects in/out.
__global__ void einsum_kernel(const float* __restrict__ mm) {
  const int which = blockIdx.z & 1;
  const int b = blockIdx.z >> 1;
  const float* A = mm + (size_t)b * NN * (2 * NE) + which * NE;   // row stride 2*NE
  const float* Bop = (which ? g_out_st : g_in_st) + (size_t)b * NE * HH;
  float* C = (which ? g_aout : g_ain) + b * NN * HH;
  const int m0 = blockIdx.y << 6;   // within 512
  const int n0 = blockIdx.x << 6;   // within 128
  auto aload = [&](int r, int k) {
    return *reinterpret_cast<const float4*>(&A[(size_t)(m0 + r) * (2 * NE) + k]);
  };
  auto bload = [&](int k, int n) {
    return *reinterpret_cast<const float4*>(&Bop[k * HH + n0 + n]);
  };
  auto epi = [&](float (&acc)[4][4], int ty, int tx) {
#pragma unroll
    for (int i = 0; i < 4; i++)
#pragma unroll
      for (int j = 0; j < 4; j++)
        C[(m0 + (ty << 2) + i) * HH + n0 + (tx << 2) + j] = acc[i][j];
  };
  gemm64(aload, bload, epi, NE);
}

// Gate GEMMs over composed A = [a_in | a_out | p3], p3 = h (z,r) or r*h (t).
// MODE 0: z = sigmoid(.)     -> g_z
// MODE 1: rh = sigmoid(.)*h  -> g_rh
// MODE 2: h = (1-z)*h + z*tanh(.)   (in-place elementwise update)
template <int MODE>
__global__ void gate_kernel(const float* __restrict__ W, const float* __restrict__ bias) {
  const int m0 = blockIdx.y << 6;
  const int n0 = blockIdx.x << 6;
  const float* p3 = (MODE == 2) ? g_rh : g_h;
  auto aload = [&](int r, int k) -> float4 {
    int row = m0 + r;
    const float* base;
    if (k < 128)       base = &g_ain[row * HH + k];
    else if (k < 256)  base = &g_aout[row * HH + (k - 128)];
    else               base = &p3[row * HH + (k - 256)];
    return *reinterpret_cast<const float4*>(base);
  };
  auto bload = [&](int k, int n) {
    return *reinterpret_cast<const float4*>(&W[k * HH + n0 + n]);
  };
  auto epi = [&](float (&acc)[4][4], int ty, int tx) {
#pragma unroll
    for (int i = 0; i < 4; i++) {
      int row = m0 + (ty << 2) + i;
#pragma unroll
      for (int j = 0; j < 4; j++) {
        int col = n0 + (tx << 2) + j;
        float v = acc[i][j] + bias[col];
        int idx = row * HH + col;
        if (MODE == 0) {
          g_z[idx] = sigmoidf_(v);
        } else if (MODE == 1) {
          g_rh[idx] = sigmoidf_(v) * g_h[idx];
        } else {
          float t = tanhf(v);
          float z = g_z[idx];
          g_h[idx] = (1.0f - z) * g_h[idx] + z * t;
        }
      }
    }
  };
  gemm64(aload, bload, epi, 3 * HH);
}

// feat = tanh([h, a] @ W1 + b1); out = sum_j feat[j]*W2[j] + b2
__global__ void final_kernel(const float* __restrict__ a,
                             const float* __restrict__ W1,
                             const float* __restrict__ b1,
                             const float* __restrict__ W2,
                             const float* __restrict__ b2,
                             float* __restrict__ out) {
  const int row = blockIdx.x;      // 0..8191
  const int j = threadIdx.x;       // 0..127
  __shared__ float sh[HH + 1];
  __shared__ float red[HH];
  sh[j] = g_h[row * HH + j];
  if (j == 0) sh[HH] = a[row];     // ANNO == 1
  __syncthreads();
  float acc = b1[j];
#pragma unroll 4
  for (int k = 0; k < HH + 1; k++) acc += sh[k] * W1[k * HH + j];
  red[j] = tanhf(acc) * W2[j];
  __syncthreads();
  for (int s = 64; s > 0; s >>= 1) {
    if (j < s) red[j] += red[j + s];
    __syncthreads();
  }
  if (j == 0) out[row] = red[0] + b2[0];
}

// ---------------- launch ----------------
extern "C" void kernel_launch(void* const* d_in, const int* in_sizes, int n_in,
                              void* d_out, int out_size) {
  const float* x     = (const float*)d_in[0];
  const float* a     = (const float*)d_in[1];
  const float* m     = (const float*)d_in[2];
  const float* W_in  = (const float*)d_in[3];
  const float* b_in  = (const float*)d_in[4];
  const float* W_out = (const float*)d_in[5];
  const float* b_out = (const float*)d_in[6];
  const float* W_z   = (const float*)d_in[7];
  const float* b_z   = (const float*)d_in[8];
  const float* W_r   = (const float*)d_in[9];
  const float* b_r   = (const float*)d_in[10];
  const float* W_t   = (const float*)d_in[11];
  const float* b_t   = (const float*)d_in[12];
  const float* W1    = (const float*)d_in[13];
  const float* b1    = (const float*)d_in[14];
  const float* W2    = (const float*)d_in[15];
  const float* b2    = (const float*)d_in[16];
  float* out = (float*)d_out;

  copy_h_kernel<<<NR * HH / 256, 256>>>(x);

  dim3 gp(8, 128);       // proj:   512/64 x 8192/64
  dim3 ge(2, 8, 2 * BB); // einsum: 128/64 x 512/64 x (2*batch)
  dim3 gg(2, 128);       // gates:  128/64 x 8192/64

  for (int s = 0; s < STEPS; s++) {
    proj_kernel<0><<<gp, 256>>>(W_in, b_in);
    proj_kernel<1><<<gp, 256>>>(W_out, b_out);
    einsum_kernel<<<ge, 256>>>(m);
    gate_kernel<0><<<gg, 256>>>(W_z, b_z);
    gate_kernel<1><<<gg, 256>>>(W_r, b_r);
    gate_kernel<2><<<gg, 256>>>(W_t, b_t);
  }

  final_kernel<<<NR, 128>>>(a, W1, b1, W2, b2, out);
}